// round 1
// baseline (speedup 1.0000x reference)
#include <cuda_runtime.h>
#include <math.h>

#define CDIM 160
#define HW 12544
#define WIMG 112
#define NIMG 32
#define BN 128
#define PAD 168
#define NTHREADS 256

// Intermediate y = [W_t;W_b;W_r;W_l;W_c] @ gelu(bn(x)), layout [B,160,HW]
__device__ float g_y[(size_t)NIMG * CDIM * HW];

__device__ __forceinline__ unsigned long long pack2(float lo, float hi) {
    unsigned long long r;
    asm("mov.b64 %0, {%1, %2};" : "=l"(r) : "f"(lo), "f"(hi));
    return r;
}
__device__ __forceinline__ void unpack2(unsigned long long v, float& lo, float& hi) {
    asm("mov.b64 {%0, %1}, %2;" : "=f"(lo), "=f"(hi) : "l"(v));
}
__device__ __forceinline__ void fma2(unsigned long long& d, unsigned long long a, unsigned long long b) {
    asm("fma.rn.f32x2 %0, %1, %2, %0;" : "+l"(d) : "l"(a), "l"(b));
}

__device__ __forceinline__ float gelu_exact(float h) {
    return 0.5f * h * (1.0f + erff(h * 0.70710678118654752f));
}

// ---------------------------------------------------------------------------
// Shared main-loop + epilogue (identical for both GEMMs)
// As: [k][m] transposed, row pitch PAD. Bs: [k][n] pitch BN. bias: [160].
// Writes out[(m)*HW-strided] at column base (b, p0).
// ---------------------------------------------------------------------------
__device__ __forceinline__ void gemm_core(const float* As, const float* Bs,
                                          const float* bias, float* outbase,
                                          int tid) {
    const int tn = tid & 15;          // n = tn + 16*j
    const int m0 = (tid >> 4) * 10;   // 10 output channels per thread (5 f32x2 pairs)

    unsigned long long acc[5][8] = {};

#pragma unroll 2
    for (int k = 0; k < CDIM; ++k) {
        unsigned long long av[5];
        const float* arow = As + k * PAD + m0;
#pragma unroll
        for (int i = 0; i < 5; ++i)
            av[i] = *reinterpret_cast<const unsigned long long*>(arow + 2 * i);

        unsigned long long bp[8];
        const float* brow = Bs + k * BN + tn;
#pragma unroll
        for (int j = 0; j < 8; ++j) {
            float bv = brow[16 * j];
            bp[j] = pack2(bv, bv);
        }
#pragma unroll
        for (int i = 0; i < 5; ++i)
#pragma unroll
            for (int j = 0; j < 8; ++j)
                fma2(acc[i][j], av[i], bp[j]);
    }

#pragma unroll
    for (int i = 0; i < 5; ++i) {
        const int m = m0 + 2 * i;
        const float blo = bias[m];
        const float bhi = bias[m + 1];
        float* r0 = outbase + (size_t)m * HW + tn;
        float* r1 = outbase + (size_t)(m + 1) * HW + tn;
#pragma unroll
        for (int j = 0; j < 8; ++j) {
            float lo, hi;
            unpack2(acc[i][j], lo, hi);
            r0[16 * j] = lo + blo;
            r1[16 * j] = hi + bhi;
        }
    }
}

// ---------------------------------------------------------------------------
// GEMM1: y = W_cat @ gelu(bn(x)) + b_cat   (BN+GELU fused in B-tile load)
// ---------------------------------------------------------------------------
__global__ __launch_bounds__(NTHREADS) void gemm1_kernel(
    const float* __restrict__ x,
    const float* __restrict__ gamma, const float* __restrict__ beta,
    const float* __restrict__ rmean, const float* __restrict__ rvar,
    const float* __restrict__ Wt, const float* __restrict__ bt,
    const float* __restrict__ Wb, const float* __restrict__ bb,
    const float* __restrict__ Wr, const float* __restrict__ br,
    const float* __restrict__ Wl, const float* __restrict__ bl,
    const float* __restrict__ Wc, const float* __restrict__ bc) {
    extern __shared__ float smem[];
    float* As = smem;                 // PAD * 160
    float* Bs = As + PAD * CDIM;      // 160 * BN
    float* bias = Bs + CDIM * BN;     // 160
    float* scale = bias + CDIM;       // 160
    float* shiftv = scale + CDIM;     // 160

    const int tid = threadIdx.x;
    const float* Wp[5] = {Wt, Wb, Wr, Wl, Wc};
    const float* bp[5] = {bt, bb, br, bl, bc};

    // A (transposed) + bias + BN params
    for (int idx = tid; idx < CDIM * CDIM; idx += NTHREADS) {
        int m = idx / CDIM;
        int k = idx - m * CDIM;
        As[k * PAD + m] = Wp[m >> 5][(m & 31) * CDIM + k];
    }
    if (tid < CDIM) {
        bias[tid] = bp[tid >> 5][tid & 31];
        float s = gamma[tid] * rsqrtf(rvar[tid] + 1e-5f);
        scale[tid] = s;
        shiftv[tid] = beta[tid] - rmean[tid] * s;
    }
    __syncthreads();

    // B tile: gelu(bn(x)) for 160 channels x 128 pixels
    const int col0 = blockIdx.x * BN;
    const int b = col0 / HW;
    const int p0 = col0 - b * HW;     // tile never crosses image boundary (12544 % 128 == 0)
    const float* xb = x + (size_t)b * CDIM * HW + p0;
    for (int i = 0; i < (CDIM * BN) / NTHREADS; ++i) {
        int idx = i * NTHREADS + tid;
        int k = idx >> 7;
        int n = idx & (BN - 1);
        float v = xb[(size_t)k * HW + n];
        float h = fmaf(v, scale[k], shiftv[k]);
        Bs[idx] = gelu_exact(h);
    }
    __syncthreads();

    gemm_core(As, Bs, bias, g_y + (size_t)b * CDIM * HW + p0, tid);
}

// ---------------------------------------------------------------------------
// GEMM2: out = W_fuse @ shifted_gather(y) + b_fuse  (shifts fused in B load)
// segment per k-channel block of 32: t:+row, b:-row, r:-col, l:+col, c:0
// ---------------------------------------------------------------------------
__global__ __launch_bounds__(NTHREADS) void gemm2_kernel(
    const float* __restrict__ Wf, const float* __restrict__ bf,
    float* __restrict__ out) {
    extern __shared__ float smem[];
    float* As = smem;
    float* Bs = As + PAD * CDIM;
    float* bias = Bs + CDIM * BN;

    const int tid = threadIdx.x;

    for (int idx = tid; idx < CDIM * CDIM; idx += NTHREADS) {
        int m = idx / CDIM;
        int k = idx - m * CDIM;
        As[k * PAD + m] = Wf[m * CDIM + k];
    }
    if (tid < CDIM) bias[tid] = bf[tid];
    __syncthreads();

    const int col0 = blockIdx.x * BN;
    const int b = col0 / HW;
    const int p0 = col0 - b * HW;
    const float* yb = g_y + (size_t)b * CDIM * HW;

    for (int i = 0; i < (CDIM * BN) / NTHREADS; ++i) {
        int idx = i * NTHREADS + tid;
        int k = idx >> 7;
        int n = idx & (BN - 1);
        int p = p0 + n;
        int h = p / WIMG;
        int w = p - h * WIMG;
        int seg = k >> 5;
        int pp;
        bool ok;
        if (seg == 0)      { ok = (h < WIMG - 1); pp = p + WIMG; }  // t: shift up
        else if (seg == 1) { ok = (h > 0);        pp = p - WIMG; }  // b: shift down
        else if (seg == 2) { ok = (w > 0);        pp = p - 1;    }  // r: shift right
        else if (seg == 3) { ok = (w < WIMG - 1); pp = p + 1;    }  // l: shift left
        else               { ok = true;           pp = p;        }  // c
        Bs[idx] = ok ? yb[(size_t)k * HW + pp] : 0.0f;
    }
    __syncthreads();

    gemm_core(As, Bs, bias, out + (size_t)b * CDIM * HW + p0, tid);
}

// ---------------------------------------------------------------------------
extern "C" void kernel_launch(void* const* d_in, const int* in_sizes, int n_in,
                              void* d_out, int out_size) {
    const float* x     = (const float*)d_in[0];
    const float* gamma = (const float*)d_in[1];
    const float* beta  = (const float*)d_in[2];
    const float* rmean = (const float*)d_in[3];
    const float* rvar  = (const float*)d_in[4];
    const float* Wt = (const float*)d_in[5];  const float* bt = (const float*)d_in[6];
    const float* Wb = (const float*)d_in[7];  const float* bb = (const float*)d_in[8];
    const float* Wr = (const float*)d_in[9];  const float* br = (const float*)d_in[10];
    const float* Wl = (const float*)d_in[11]; const float* bl = (const float*)d_in[12];
    const float* Wc = (const float*)d_in[13]; const float* bc = (const float*)d_in[14];
    const float* Wf = (const float*)d_in[15]; const float* bf = (const float*)d_in[16];

    const size_t smem1 = (size_t)(PAD * CDIM + CDIM * BN + 3 * CDIM) * sizeof(float);
    const size_t smem2 = (size_t)(PAD * CDIM + CDIM * BN + CDIM) * sizeof(float);
    cudaFuncSetAttribute(gemm1_kernel, cudaFuncAttributeMaxDynamicSharedMemorySize, (int)smem1);
    cudaFuncSetAttribute(gemm2_kernel, cudaFuncAttributeMaxDynamicSharedMemorySize, (int)smem2);

    const int nblocks = (NIMG * HW) / BN;  // 3136
    gemm1_kernel<<<nblocks, NTHREADS, smem1>>>(x, gamma, beta, rmean, rvar,
                                               Wt, bt, Wb, bb, Wr, br, Wl, bl, Wc, bc);
    gemm2_kernel<<<nblocks, NTHREADS, smem2>>>(Wf, bf, (float*)d_out);
}

// round 3
// speedup vs baseline: 1.2167x; 1.2167x over previous
#include <cuda_runtime.h>
#include <cuda_bf16.h>
#include <math.h>
#include <cstdint>

#define CDIM 160
#define HW 12544
#define WIMG 112
#define NIMG 32
#define NTHREADS 256
#define TILES_PER_CTA 4
#define NTILES_TOTAL 3136

#define PA 168      // A smem pitch (bf16 elems) -> 336B rows, conflict-free ldmatrix
#define PB 136      // B smem pitch (bf16 elems) -> 272B rows, conflict-free stores + ldmatrix.trans
#define PD 136      // D staging pitch (f32)

// shared memory byte offsets
#define SM_BIAS  0
#define SM_SCALE 640
#define SM_SHIFT 1280
#define SM_ASH   2048
#define SM_ASL   (SM_ASH + CDIM * PA * 2)   // 55808
#define SM_BSH   (SM_ASL + CDIM * PA * 2)   // 109568
#define SM_BSL   (SM_BSH + CDIM * PB * 2)   // 153088
#define SM_DST   SM_BSH                      // D staging aliases B tiles (87040 B)
#define SM_TOTAL (SM_BSL + CDIM * PB * 2)   // 196608

// intermediate y, channel-major [b][c][hw], packed (bf16 hi | bf16 lo << 16)
__device__ uint32_t g_y2[(size_t)NIMG * CDIM * HW];

// ---------------------------------------------------------------------------
__device__ __forceinline__ uint32_t smem_u32(const void* p) {
    uint32_t a;
    asm("{ .reg .u64 t; cvta.to.shared.u64 t, %1; cvt.u32.u64 %0, t; }" : "=r"(a) : "l"(p));
    return a;
}
__device__ __forceinline__ void ldsm_x4(uint32_t* r, uint32_t addr) {
    asm volatile("ldmatrix.sync.aligned.m8n8.x4.shared.b16 {%0,%1,%2,%3}, [%4];"
        : "=r"(r[0]), "=r"(r[1]), "=r"(r[2]), "=r"(r[3]) : "r"(addr));
}
__device__ __forceinline__ void ldsm_x4t(uint32_t* r, uint32_t addr) {
    asm volatile("ldmatrix.sync.aligned.m8n8.x4.trans.shared.b16 {%0,%1,%2,%3}, [%4];"
        : "=r"(r[0]), "=r"(r[1]), "=r"(r[2]), "=r"(r[3]) : "r"(addr));
}
__device__ __forceinline__ void mma16816(float* d, const uint32_t* a, const uint32_t* b) {
    asm volatile("mma.sync.aligned.m16n8k16.row.col.f32.bf16.bf16.f32 "
        "{%0,%1,%2,%3}, {%4,%5,%6,%7}, {%8,%9}, {%0,%1,%2,%3};"
        : "+f"(d[0]), "+f"(d[1]), "+f"(d[2]), "+f"(d[3])
        : "r"(a[0]), "r"(a[1]), "r"(a[2]), "r"(a[3]), "r"(b[0]), "r"(b[1]));
}
__device__ __forceinline__ uint32_t split_pack(float v) {
    __nv_bfloat16 hb = __float2bfloat16(v);
    float hf = __bfloat162float(hb);
    __nv_bfloat16 lb = __float2bfloat16(v - hf);
    return (uint32_t)__bfloat16_as_ushort(hb) | ((uint32_t)__bfloat16_as_ushort(lb) << 16);
}

// ---------------------------------------------------------------------------
// 3-pass bf16x3 MMA over a 160x128 tile. acc[5][4][4] per thread.
// ---------------------------------------------------------------------------
__device__ __forceinline__ void mma_passes(uint32_t sb, float acc[5][4][4],
                                           int wid, int lane) {
    const int wm = wid >> 2;          // 0..1  -> m offset wm*80
    const int wn = wid & 3;           // 0..3  -> n offset wn*32
    const uint32_t a_lane = (uint32_t)((wm * 80 + (lane & 15)) * (PA * 2) + (lane >> 4) * 16);
    const uint32_t b_lane = (uint32_t)((lane & 15) * (PB * 2) + (wn * 32 + (lane >> 4) * 8) * 2);

#pragma unroll
    for (int pass = 0; pass < 3; ++pass) {
        const uint32_t Ab = sb + (pass < 2 ? SM_ASH : SM_ASL) + a_lane;
        const uint32_t Bb = sb + (pass == 1 ? SM_BSL : SM_BSH) + b_lane;
#pragma unroll 2
        for (int k0 = 0; k0 < CDIM; k0 += 16) {
            uint32_t a[5][4];
#pragma unroll
            for (int mi = 0; mi < 5; ++mi)
                ldsm_x4(a[mi], Ab + mi * 16 * (PA * 2) + k0 * 2);
            uint32_t b[2][4];   // b[p] covers n-tiles 2p, 2p+1
#pragma unroll
            for (int p = 0; p < 2; ++p)
                ldsm_x4t(b[p], Bb + k0 * (PB * 2) + p * 32);
#pragma unroll
            for (int mi = 0; mi < 5; ++mi)
#pragma unroll
                for (int ni = 0; ni < 4; ++ni)
                    mma16816(acc[mi][ni], a[mi], b[ni >> 1] + (ni & 1) * 2);
        }
    }
}

// dump accumulators to smem D staging [m][n] f32 pitch PD
__device__ __forceinline__ void dump_D(float* Dst, const float acc[5][4][4],
                                       int wid, int lane) {
    const int wm = wid >> 2, wn = wid & 3;
    const int tr = lane >> 2, tc = 2 * (lane & 3);
#pragma unroll
    for (int mi = 0; mi < 5; ++mi) {
#pragma unroll
        for (int ni = 0; ni < 4; ++ni) {
            const int r = wm * 80 + mi * 16 + tr;
            const int c = wn * 32 + ni * 8 + tc;
            *(float2*)(Dst + r * PD + c)       = make_float2(acc[mi][ni][0], acc[mi][ni][1]);
            *(float2*)(Dst + (r + 8) * PD + c) = make_float2(acc[mi][ni][2], acc[mi][ni][3]);
        }
    }
}

// ---------------------------------------------------------------------------
// Kernel 1: y2 = split( W_cat @ gelu(bn(x)) + b_cat )
// ---------------------------------------------------------------------------
__global__ __launch_bounds__(NTHREADS) void gemm1_mma(
    const float* __restrict__ x,
    const float* __restrict__ gamma, const float* __restrict__ beta,
    const float* __restrict__ rmean, const float* __restrict__ rvar,
    const float* __restrict__ Wt, const float* __restrict__ bt,
    const float* __restrict__ Wb, const float* __restrict__ bb,
    const float* __restrict__ Wr, const float* __restrict__ br,
    const float* __restrict__ Wl, const float* __restrict__ bl,
    const float* __restrict__ Wc, const float* __restrict__ bc) {
    extern __shared__ char smem[];
    const uint32_t sb = smem_u32(smem);
    const int tid = threadIdx.x;
    const int wid = tid >> 5, lane = tid & 31;
    float* bias_s  = (float*)(smem + SM_BIAS);
    float* scale_s = (float*)(smem + SM_SCALE);
    float* shift_s = (float*)(smem + SM_SHIFT);
    __nv_bfloat16* Ah = (__nv_bfloat16*)(smem + SM_ASH);
    __nv_bfloat16* Al = (__nv_bfloat16*)(smem + SM_ASL);
    __nv_bfloat16* Bh = (__nv_bfloat16*)(smem + SM_BSH);
    __nv_bfloat16* Bl = (__nv_bfloat16*)(smem + SM_BSL);
    float* Dst = (float*)(smem + SM_DST);

    // weights -> smem (hi/lo split), once per CTA
    const float* Wseg[5] = {Wt, Wb, Wr, Wl, Wc};
    for (int idx = tid; idx < CDIM * CDIM; idx += NTHREADS) {
        int m = idx / CDIM;
        int k = idx - m * CDIM;
        float v = Wseg[m >> 5][(m & 31) * CDIM + k];
        __nv_bfloat16 hb = __float2bfloat16(v);
        Ah[m * PA + k] = hb;
        Al[m * PA + k] = __float2bfloat16(v - __bfloat162float(hb));
    }
    if (tid < CDIM) {
        const float* bp[5] = {bt, bb, br, bl, bc};
        bias_s[tid] = bp[tid >> 5][tid & 31];
        float s = gamma[tid] * rsqrtf(rvar[tid] + 1e-5f);
        scale_s[tid] = s;
        shift_s[tid] = beta[tid] - rmean[tid] * s;
    }
    __syncthreads();

    const int px = tid & 127, half = tid >> 7;

    for (int t = 0; t < TILES_PER_CTA; ++t) {
        const int tile = blockIdx.x * TILES_PER_CTA + t;
        const int b = (tile * 128) / HW;
        const int p0 = tile * 128 - b * HW;

        // B prep: BN + exact GELU + hi/lo split -> Bs[k][px]
        const float* xb = x + (size_t)b * CDIM * HW + p0;
#pragma unroll 4
        for (int i = 0; i < 80; ++i) {
            const int k = i + 80 * half;
            float v = xb[(size_t)k * HW + px];
            float h = fmaf(v, scale_s[k], shift_s[k]);
            float g = 0.5f * h * (1.0f + erff(h * 0.70710678118654752f));
            __nv_bfloat16 hb = __float2bfloat16(g);
            Bh[k * PB + px] = hb;
            Bl[k * PB + px] = __float2bfloat16(g - __bfloat162float(hb));
        }
        __syncthreads();

        float acc[5][4][4] = {};
        mma_passes(sb, acc, wid, lane);
        __syncthreads();            // all B reads done before staging overwrite

        dump_D(Dst, acc, wid, lane);
        __syncthreads();

        // epilogue: +bias, split-pack, coalesced store to y2
        uint32_t* yb = g_y2 + (size_t)b * CDIM * HW + p0;
#pragma unroll 4
        for (int i = 0; i < 80; ++i) {
            const int idx = i * NTHREADS + tid;
            const int m = idx >> 7;
            const int n = idx & 127;
            float v = Dst[m * PD + n] + bias_s[m];
            yb[(size_t)m * HW + n] = split_pack(v);
        }
        __syncthreads();            // staging free before next tile's prep
    }
}

// ---------------------------------------------------------------------------
// Kernel 2: out = W_fuse @ shifted_gather(y2) + b_fuse
// ---------------------------------------------------------------------------
__global__ __launch_bounds__(NTHREADS) void gemm2_mma(
    const float* __restrict__ Wf, const float* __restrict__ bf,
    float* __restrict__ out) {
    extern __shared__ char smem[];
    const uint32_t sb = smem_u32(smem);
    const int tid = threadIdx.x;
    const int wid = tid >> 5, lane = tid & 31;
    float* bias_s = (float*)(smem + SM_BIAS);
    __nv_bfloat16* Ah = (__nv_bfloat16*)(smem + SM_ASH);
    __nv_bfloat16* Al = (__nv_bfloat16*)(smem + SM_ASL);
    __nv_bfloat16* Bh = (__nv_bfloat16*)(smem + SM_BSH);
    __nv_bfloat16* Bl = (__nv_bfloat16*)(smem + SM_BSL);
    float* Dst = (float*)(smem + SM_DST);

    for (int idx = tid; idx < CDIM * CDIM; idx += NTHREADS) {
        int m = idx / CDIM;
        int k = idx - m * CDIM;
        float v = Wf[m * CDIM + k];
        __nv_bfloat16 hb = __float2bfloat16(v);
        Ah[m * PA + k] = hb;
        Al[m * PA + k] = __float2bfloat16(v - __bfloat162float(hb));
    }
    if (tid < CDIM) bias_s[tid] = bf[tid];
    __syncthreads();

    const int px = tid & 127, half = tid >> 7;

    for (int t = 0; t < TILES_PER_CTA; ++t) {
        const int tile = blockIdx.x * TILES_PER_CTA + t;
        const int b = (tile * 128) / HW;
        const int p0 = tile * 128 - b * HW;

        // B prep: shifted gather of packed y2 -> Bs[k][px]
        const uint32_t* yb = g_y2 + (size_t)b * CDIM * HW;
        const int p = p0 + px;
        const int hr = p / WIMG;
        const int w = p - hr * WIMG;
#pragma unroll 4
        for (int i = 0; i < 80; ++i) {
            const int k = i + 80 * half;
            const int seg = k >> 5;
            int pp; bool ok;
            if (seg == 0)      { ok = (hr < WIMG - 1); pp = p + WIMG; }
            else if (seg == 1) { ok = (hr > 0);        pp = p - WIMG; }
            else if (seg == 2) { ok = (w > 0);         pp = p - 1;    }
            else if (seg == 3) { ok = (w < WIMG - 1);  pp = p + 1;    }
            else               { ok = true;            pp = p;        }
            uint32_t v = ok ? yb[(size_t)k * HW + pp] : 0u;
            Bh[k * PB + px] = __ushort_as_bfloat16((unsigned short)(v & 0xFFFF));
            Bl[k * PB + px] = __ushort_as_bfloat16((unsigned short)(v >> 16));
        }
        __syncthreads();

        float acc[5][4][4] = {};
        mma_passes(sb, acc, wid, lane);
        __syncthreads();

        dump_D(Dst, acc, wid, lane);
        __syncthreads();

        float* ob = out + (size_t)b * CDIM * HW + p0;
#pragma unroll 4
        for (int i = 0; i < 80; ++i) {
            const int idx = i * NTHREADS + tid;
            const int m = idx >> 7;
            const int n = idx & 127;
            ob[(size_t)m * HW + n] = Dst[m * PD + n] + bias_s[m];
        }
        __syncthreads();
    }
}

// ---------------------------------------------------------------------------
extern "C" void kernel_launch(void* const* d_in, const int* in_sizes, int n_in,
                              void* d_out, int out_size) {
    const float* x     = (const float*)d_in[0];
    const float* gamma = (const float*)d_in[1];
    const float* beta  = (const float*)d_in[2];
    const float* rmean = (const float*)d_in[3];
    const float* rvar  = (const float*)d_in[4];
    const float* Wt = (const float*)d_in[5];  const float* bt = (const float*)d_in[6];
    const float* Wb = (const float*)d_in[7];  const float* bb = (const float*)d_in[8];
    const float* Wr = (const float*)d_in[9];  const float* br = (const float*)d_in[10];
    const float* Wl = (const float*)d_in[11]; const float* bl = (const float*)d_in[12];
    const float* Wc = (const float*)d_in[13]; const float* bc = (const float*)d_in[14];
    const float* Wf = (const float*)d_in[15]; const float* bf = (const float*)d_in[16];

    cudaFuncSetAttribute(gemm1_mma, cudaFuncAttributeMaxDynamicSharedMemorySize, SM_TOTAL);
    cudaFuncSetAttribute(gemm2_mma, cudaFuncAttributeMaxDynamicSharedMemorySize, SM_TOTAL);

    const int nblocks = NTILES_TOTAL / TILES_PER_CTA;  // 784
    gemm1_mma<<<nblocks, NTHREADS, SM_TOTAL>>>(x, gamma, beta, rmean, rvar,
                                               Wt, bt, Wb, bb, Wr, br, Wl, bl, Wc, bc);
    gemm2_mma<<<nblocks, NTHREADS, SM_TOTAL>>>(Wf, bf, (float*)d_out);
}

// round 4
// speedup vs baseline: 2.8759x; 2.3638x over previous
#include <cuda_runtime.h>
#include <cuda_bf16.h>
#include <math.h>
#include <cstdint>

#define CDIM 160
#define HW 12544
#define WIMG 112
#define NIMG 32
#define NTHREADS 512
#define TILES_PER_CTA 4
#define NTILES_TOTAL 3136

#define PA 168      // A smem pitch (bf16) -> 336B rows, conflict-free ldmatrix
#define PB 136      // B smem pitch (bf16) -> 272B rows, conflict-free ldmatrix.trans

// shared memory byte offsets
#define SM_BIAS  0
#define SM_SCALE 640
#define SM_SHIFT 1280
#define SM_ASH   2048
#define SM_ASL   (SM_ASH + CDIM * PA * 2)   // +53760
#define SM_BSH   (SM_ASL + CDIM * PA * 2)
#define SM_BSL   (SM_BSH + CDIM * PB * 2)   // +43520
#define SM_TOTAL (SM_BSL + CDIM * PB * 2)   // 196608

// intermediate y, channel-major [b][c][hw], packed (bf16 hi | bf16 lo << 16)
__device__ uint32_t g_y2[(size_t)NIMG * CDIM * HW];

// ---------------------------------------------------------------------------
__device__ __forceinline__ uint32_t smem_u32(const void* p) {
    uint32_t a;
    asm("{ .reg .u64 t; cvta.to.shared.u64 t, %1; cvt.u32.u64 %0, t; }" : "=r"(a) : "l"(p));
    return a;
}
__device__ __forceinline__ void ldsm_x4(uint32_t* r, uint32_t addr) {
    asm volatile("ldmatrix.sync.aligned.m8n8.x4.shared.b16 {%0,%1,%2,%3}, [%4];"
        : "=r"(r[0]), "=r"(r[1]), "=r"(r[2]), "=r"(r[3]) : "r"(addr));
}
__device__ __forceinline__ void ldsm_x4t(uint32_t* r, uint32_t addr) {
    asm volatile("ldmatrix.sync.aligned.m8n8.x4.trans.shared.b16 {%0,%1,%2,%3}, [%4];"
        : "=r"(r[0]), "=r"(r[1]), "=r"(r[2]), "=r"(r[3]) : "r"(addr));
}
__device__ __forceinline__ void mma16816(float* d, const uint32_t* a, const uint32_t* b) {
    asm volatile("mma.sync.aligned.m16n8k16.row.col.f32.bf16.bf16.f32 "
        "{%0,%1,%2,%3}, {%4,%5,%6,%7}, {%8,%9}, {%0,%1,%2,%3};"
        : "+f"(d[0]), "+f"(d[1]), "+f"(d[2]), "+f"(d[3])
        : "r"(a[0]), "r"(a[1]), "r"(a[2]), "r"(a[3]), "r"(b[0]), "r"(b[1]));
}
__device__ __forceinline__ uint32_t split_pack(float v) {
    __nv_bfloat16 hb = __float2bfloat16(v);
    float hf = __bfloat162float(hb);
    __nv_bfloat16 lb = __float2bfloat16(v - hf);
    return (uint32_t)__bfloat16_as_ushort(hb) | ((uint32_t)__bfloat16_as_ushort(lb) << 16);
}

// ---------------------------------------------------------------------------
// 3-pass bf16x3 MMA over a 160x128 tile. 16 warps: 2M x 8N.
// Each warp: 5 m-tiles (16 rows) x 2 n-tiles (8 cols). acc[5][2][4].
// ---------------------------------------------------------------------------
__device__ __forceinline__ void mma_passes(uint32_t sb, float acc[5][2][4],
                                           int wid, int lane) {
    const int wm = wid >> 3;          // 0..1 -> m offset wm*80
    const int wn = wid & 7;           // 0..7 -> n offset wn*16
    const uint32_t a_lane = (uint32_t)((wm * 80 + (lane & 15)) * (PA * 2) + (lane >> 4) * 16);
    const uint32_t b_lane = (uint32_t)((lane & 15) * (PB * 2) + (wn * 16 + (lane >> 4) * 8) * 2);

#pragma unroll
    for (int pass = 0; pass < 3; ++pass) {
        const uint32_t Ab = sb + (pass < 2 ? SM_ASH : SM_ASL) + a_lane;
        const uint32_t Bb = sb + (pass == 1 ? SM_BSL : SM_BSH) + b_lane;
#pragma unroll 2
        for (int k0 = 0; k0 < CDIM; k0 += 16) {
            uint32_t a[5][4];
#pragma unroll
            for (int mi = 0; mi < 5; ++mi)
                ldsm_x4(a[mi], Ab + mi * 16 * (PA * 2) + k0 * 2);
            uint32_t b[4];
            ldsm_x4t(b, Bb + k0 * (PB * 2));
#pragma unroll
            for (int mi = 0; mi < 5; ++mi) {
                mma16816(acc[mi][0], a[mi], b);
                mma16816(acc[mi][1], a[mi], b + 2);
            }
        }
    }
}

// ---------------------------------------------------------------------------
// Kernel 1: y2 = split( W_cat @ gelu(bn(x)) + b_cat )
// ---------------------------------------------------------------------------
__global__ __launch_bounds__(NTHREADS, 1) void gemm1_mma(
    const float* __restrict__ x,
    const float* __restrict__ gamma, const float* __restrict__ beta,
    const float* __restrict__ rmean, const float* __restrict__ rvar,
    const float* __restrict__ Wt, const float* __restrict__ bt,
    const float* __restrict__ Wb, const float* __restrict__ bb,
    const float* __restrict__ Wr, const float* __restrict__ br,
    const float* __restrict__ Wl, const float* __restrict__ bl,
    const float* __restrict__ Wc, const float* __restrict__ bc) {
    extern __shared__ char smem[];
    const uint32_t sb = smem_u32(smem);
    const int tid = threadIdx.x;
    const int wid = tid >> 5, lane = tid & 31;
    float* bias_s  = (float*)(smem + SM_BIAS);
    float* scale_s = (float*)(smem + SM_SCALE);
    float* shift_s = (float*)(smem + SM_SHIFT);
    __nv_bfloat16* Ah = (__nv_bfloat16*)(smem + SM_ASH);
    __nv_bfloat16* Al = (__nv_bfloat16*)(smem + SM_ASL);
    __nv_bfloat16* Bh = (__nv_bfloat16*)(smem + SM_BSH);
    __nv_bfloat16* Bl = (__nv_bfloat16*)(smem + SM_BSL);

    // weights -> smem (hi/lo split), once per CTA
    const float* Wseg[5] = {Wt, Wb, Wr, Wl, Wc};
    for (int idx = tid; idx < CDIM * CDIM; idx += NTHREADS) {
        int m = idx / CDIM;
        int k = idx - m * CDIM;
        float v = Wseg[m >> 5][(m & 31) * CDIM + k];
        __nv_bfloat16 hb = __float2bfloat16(v);
        Ah[m * PA + k] = hb;
        Al[m * PA + k] = __float2bfloat16(v - __bfloat162float(hb));
    }
    if (tid < CDIM) {
        const float* bp[5] = {bt, bb, br, bl, bc};
        bias_s[tid] = bp[tid >> 5][tid & 31];
        float s = gamma[tid] * rsqrtf(rvar[tid] + 1e-5f);
        scale_s[tid] = s;
        shift_s[tid] = beta[tid] - rmean[tid] * s;
    }
    __syncthreads();

    const int px = tid & 127;
    const int kbase = (tid >> 7) * 40;    // 4 k-groups of 40
    const int wm = wid >> 3, wn = wid & 7;
    const int tr = lane >> 2, tc = 2 * (lane & 3);

    float v0[20], v1[20];

    // prefetch batch 0 of tile 0
    {
        const int tile = blockIdx.x * TILES_PER_CTA;
        const int b = (tile * 128) / HW;
        const int p0 = tile * 128 - b * HW;
        const float* xb = x + (size_t)b * CDIM * HW + p0 + px;
#pragma unroll
        for (int j = 0; j < 20; ++j) v0[j] = xb[(size_t)(kbase + j) * HW];
    }

    for (int t = 0; t < TILES_PER_CTA; ++t) {
        const int tile = blockIdx.x * TILES_PER_CTA + t;
        const int b = (tile * 128) / HW;
        const int p0 = tile * 128 - b * HW;
        const float* xb = x + (size_t)b * CDIM * HW + p0 + px;

        // issue batch 1 loads, then convert batch 0 (hides latency)
#pragma unroll
        for (int j = 0; j < 20; ++j) v1[j] = xb[(size_t)(kbase + 20 + j) * HW];
#pragma unroll
        for (int j = 0; j < 20; ++j) {
            const int k = kbase + j;
            float h = fmaf(v0[j], scale_s[k], shift_s[k]);
            float g = 0.5f * h * (1.0f + erff(h * 0.70710678118654752f));
            __nv_bfloat16 hb = __float2bfloat16(g);
            Bh[k * PB + px] = hb;
            Bl[k * PB + px] = __float2bfloat16(g - __bfloat162float(hb));
        }
#pragma unroll
        for (int j = 0; j < 20; ++j) {
            const int k = kbase + 20 + j;
            float h = fmaf(v1[j], scale_s[k], shift_s[k]);
            float g = 0.5f * h * (1.0f + erff(h * 0.70710678118654752f));
            __nv_bfloat16 hb = __float2bfloat16(g);
            Bh[k * PB + px] = hb;
            Bl[k * PB + px] = __float2bfloat16(g - __bfloat162float(hb));
        }
        __syncthreads();

        float acc[5][2][4] = {};
        mma_passes(sb, acc, wid, lane);
        __syncthreads();

        // prefetch batch 0 of next tile during epilogue
        if (t + 1 < TILES_PER_CTA) {
            const int nt = tile + 1;
            const int nb = (nt * 128) / HW;
            const int np0 = nt * 128 - nb * HW;
            const float* nxb = x + (size_t)nb * CDIM * HW + np0 + px;
#pragma unroll
            for (int j = 0; j < 20; ++j) v0[j] = nxb[(size_t)(kbase + j) * HW];
        }

        // epilogue: +bias, split-pack, direct global stores (32B sectors)
        uint32_t* yb = g_y2 + (size_t)b * CDIM * HW + p0;
#pragma unroll
        for (int mi = 0; mi < 5; ++mi) {
            const int r0 = wm * 80 + mi * 16 + tr;
            const float bia0 = bias_s[r0];
            const float bia1 = bias_s[r0 + 8];
#pragma unroll
            for (int ni = 0; ni < 2; ++ni) {
                const int c = wn * 16 + ni * 8 + tc;
                uint2 o;
                o.x = split_pack(acc[mi][ni][0] + bia0);
                o.y = split_pack(acc[mi][ni][1] + bia0);
                *(uint2*)(yb + (size_t)r0 * HW + c) = o;
                o.x = split_pack(acc[mi][ni][2] + bia1);
                o.y = split_pack(acc[mi][ni][3] + bia1);
                *(uint2*)(yb + (size_t)(r0 + 8) * HW + c) = o;
            }
        }
    }
}

// ---------------------------------------------------------------------------
// Kernel 2: out = W_fuse @ shifted_gather(y2) + b_fuse
// ---------------------------------------------------------------------------
__global__ __launch_bounds__(NTHREADS, 1) void gemm2_mma(
    const float* __restrict__ Wf, const float* __restrict__ bf,
    float* __restrict__ out) {
    extern __shared__ char smem[];
    const uint32_t sb = smem_u32(smem);
    const int tid = threadIdx.x;
    const int wid = tid >> 5, lane = tid & 31;
    float* bias_s = (float*)(smem + SM_BIAS);
    __nv_bfloat16* Ah = (__nv_bfloat16*)(smem + SM_ASH);
    __nv_bfloat16* Al = (__nv_bfloat16*)(smem + SM_ASL);
    __nv_bfloat16* Bh = (__nv_bfloat16*)(smem + SM_BSH);
    __nv_bfloat16* Bl = (__nv_bfloat16*)(smem + SM_BSL);

    for (int idx = tid; idx < CDIM * CDIM; idx += NTHREADS) {
        int m = idx / CDIM;
        int k = idx - m * CDIM;
        float v = Wf[m * CDIM + k];
        __nv_bfloat16 hb = __float2bfloat16(v);
        Ah[m * PA + k] = hb;
        Al[m * PA + k] = __float2bfloat16(v - __bfloat162float(hb));
    }
    if (tid < CDIM) bias_s[tid] = bf[tid];
    __syncthreads();

    const int px = tid & 127;
    const int kbase = (tid >> 7) * 40;
    const int wm = wid >> 3, wn = wid & 7;
    const int tr = lane >> 2, tc = 2 * (lane & 3);

    uint32_t v0[20], v1[20];

    // gather helper: shifted, masked load of packed y2
    auto gather = [&](const uint32_t* yb, int p, int hr, int w, int k) -> uint32_t {
        const int seg = k >> 5;
        int pp; bool ok;
        if (seg == 0)      { ok = (hr < WIMG - 1); pp = p + WIMG; }
        else if (seg == 1) { ok = (hr > 0);        pp = p - WIMG; }
        else if (seg == 2) { ok = (w > 0);         pp = p - 1;    }
        else if (seg == 3) { ok = (w < WIMG - 1);  pp = p + 1;    }
        else               { ok = true;            pp = p;        }
        return ok ? yb[(size_t)k * HW + pp] : 0u;
    };

    {
        const int tile = blockIdx.x * TILES_PER_CTA;
        const int b = (tile * 128) / HW;
        const int p0 = tile * 128 - b * HW;
        const uint32_t* yb = g_y2 + (size_t)b * CDIM * HW;
        const int p = p0 + px, hr = p / WIMG, w = p - hr * WIMG;
#pragma unroll
        for (int j = 0; j < 20; ++j) v0[j] = gather(yb, p, hr, w, kbase + j);
    }

    for (int t = 0; t < TILES_PER_CTA; ++t) {
        const int tile = blockIdx.x * TILES_PER_CTA + t;
        const int b = (tile * 128) / HW;
        const int p0 = tile * 128 - b * HW;
        const uint32_t* yb = g_y2 + (size_t)b * CDIM * HW;
        const int p = p0 + px, hr = p / WIMG, w = p - hr * WIMG;

#pragma unroll
        for (int j = 0; j < 20; ++j) v1[j] = gather(yb, p, hr, w, kbase + 20 + j);
#pragma unroll
        for (int j = 0; j < 20; ++j) {
            const int k = kbase + j;
            Bh[k * PB + px] = __ushort_as_bfloat16((unsigned short)(v0[j] & 0xFFFF));
            Bl[k * PB + px] = __ushort_as_bfloat16((unsigned short)(v0[j] >> 16));
        }
#pragma unroll
        for (int j = 0; j < 20; ++j) {
            const int k = kbase + 20 + j;
            Bh[k * PB + px] = __ushort_as_bfloat16((unsigned short)(v1[j] & 0xFFFF));
            Bl[k * PB + px] = __ushort_as_bfloat16((unsigned short)(v1[j] >> 16));
        }
        __syncthreads();

        float acc[5][2][4] = {};
        mma_passes(sb, acc, wid, lane);
        __syncthreads();

        if (t + 1 < TILES_PER_CTA) {
            const int nt = tile + 1;
            const int nb = (nt * 128) / HW;
            const int np0 = nt * 128 - nb * HW;
            const uint32_t* nyb = g_y2 + (size_t)nb * CDIM * HW;
            const int np = np0 + px, nhr = np / WIMG, nw = np - nhr * WIMG;
#pragma unroll
            for (int j = 0; j < 20; ++j) v0[j] = gather(nyb, np, nhr, nw, kbase + j);
        }

        float* ob = out + (size_t)b * CDIM * HW + p0;
#pragma unroll
        for (int mi = 0; mi < 5; ++mi) {
            const int r0 = wm * 80 + mi * 16 + tr;
            const float bia0 = bias_s[r0];
            const float bia1 = bias_s[r0 + 8];
#pragma unroll
            for (int ni = 0; ni < 2; ++ni) {
                const int c = wn * 16 + ni * 8 + tc;
                *(float2*)(ob + (size_t)r0 * HW + c) =
                    make_float2(acc[mi][ni][0] + bia0, acc[mi][ni][1] + bia0);
                *(float2*)(ob + (size_t)(r0 + 8) * HW + c) =
                    make_float2(acc[mi][ni][2] + bia1, acc[mi][ni][3] + bia1);
            }
        }
    }
}

// ---------------------------------------------------------------------------
extern "C" void kernel_launch(void* const* d_in, const int* in_sizes, int n_in,
                              void* d_out, int out_size) {
    const float* x     = (const float*)d_in[0];
    const float* gamma = (const float*)d_in[1];
    const float* beta  = (const float*)d_in[2];
    const float* rmean = (const float*)d_in[3];
    const float* rvar  = (const float*)d_in[4];
    const float* Wt = (const float*)d_in[5];  const float* bt = (const float*)d_in[6];
    const float* Wb = (const float*)d_in[7];  const float* bb = (const float*)d_in[8];
    const float* Wr = (const float*)d_in[9];  const float* br = (const float*)d_in[10];
    const float* Wl = (const float*)d_in[11]; const float* bl = (const float*)d_in[12];
    const float* Wc = (const float*)d_in[13]; const float* bc = (const float*)d_in[14];
    const float* Wf = (const float*)d_in[15]; const float* bf = (const float*)d_in[16];

    cudaFuncSetAttribute(gemm1_mma, cudaFuncAttributeMaxDynamicSharedMemorySize, SM_TOTAL);
    cudaFuncSetAttribute(gemm2_mma, cudaFuncAttributeMaxDynamicSharedMemorySize, SM_TOTAL);

    const int nblocks = NTILES_TOTAL / TILES_PER_CTA;  // 784
    gemm1_mma<<<nblocks, NTHREADS, SM_TOTAL>>>(x, gamma, beta, rmean, rvar,
                                               Wt, bt, Wb, bb, Wr, br, Wl, bl, Wc, bc);
    gemm2_mma<<<nblocks, NTHREADS, SM_TOTAL>>>(Wf, bf, (float*)d_out);
}

// round 5
// speedup vs baseline: 4.4953x; 1.5631x over previous
#include <cuda_runtime.h>
#include <cuda_fp16.h>
#include <math.h>
#include <cstdint>

#define CDIM 160
#define HW 12544
#define WIMG 112
#define NIMG 32
#define NTHREADS 512
#define TILES_PER_CTA 7
#define NBLOCKS 448          // 448 * 7 = 3136 tiles

#define PA 168      // A smem pitch (fp16) -> 336B rows, conflict-free ldmatrix
#define PB 136      // B smem pitch (fp16) -> 272B rows, conflict-free ldmatrix.trans
#define BSIZE (CDIM * PB * 2)   // 43520 bytes, one B half-tile

// shared memory byte offsets
#define SM_BIAS  0
#define SM_SCALE 640
#define SM_SHIFT 1280
#define SM_A     2048                       // 160*168*2 = 53760
#define SM_B0    (SM_A + CDIM * PA * 2)     // 55808: buf0 = [Bh | Bl]
#define SM_B1    (SM_B0 + 2 * BSIZE)        // 142848
#define SM_TOTAL (SM_B1 + 2 * BSIZE)        // 229888

// intermediate y, channel-major [b][c][hw], packed (fp16 hi | fp16 lo << 16)
__device__ uint32_t g_y2[(size_t)NIMG * CDIM * HW];

// ---------------------------------------------------------------------------
__device__ __forceinline__ uint32_t smem_u32(const void* p) {
    uint32_t a;
    asm("{ .reg .u64 t; cvta.to.shared.u64 t, %1; cvt.u32.u64 %0, t; }" : "=r"(a) : "l"(p));
    return a;
}
__device__ __forceinline__ void ldsm_x4(uint32_t* r, uint32_t addr) {
    asm volatile("ldmatrix.sync.aligned.m8n8.x4.shared.b16 {%0,%1,%2,%3}, [%4];"
        : "=r"(r[0]), "=r"(r[1]), "=r"(r[2]), "=r"(r[3]) : "r"(addr));
}
__device__ __forceinline__ void ldsm_x4t(uint32_t* r, uint32_t addr) {
    asm volatile("ldmatrix.sync.aligned.m8n8.x4.trans.shared.b16 {%0,%1,%2,%3}, [%4];"
        : "=r"(r[0]), "=r"(r[1]), "=r"(r[2]), "=r"(r[3]) : "r"(addr));
}
__device__ __forceinline__ void mma16816(float* d, const uint32_t* a, const uint32_t* b) {
    asm volatile("mma.sync.aligned.m16n8k16.row.col.f32.f16.f16.f32 "
        "{%0,%1,%2,%3}, {%4,%5,%6,%7}, {%8,%9}, {%0,%1,%2,%3};"
        : "+f"(d[0]), "+f"(d[1]), "+f"(d[2]), "+f"(d[3])
        : "r"(a[0]), "r"(a[1]), "r"(a[2]), "r"(a[3]), "r"(b[0]), "r"(b[1]));
}
// fp32 -> packed (fp16 hi | fp16 lo << 16)
__device__ __forceinline__ uint32_t split_pack(float v) {
    __half hh = __float2half_rn(v);
    __half lo = __float2half_rn(v - __half2float(hh));
    return (uint32_t)__half_as_ushort(hh) | ((uint32_t)__half_as_ushort(lo) << 16);
}

// ---------------------------------------------------------------------------
// 2-pass fp16 MMA over a 160x128 tile. 16 warps: 2M x 8N.
// A: fp16 unsplit. B: hi at bufbase, lo at bufbase+BSIZE.
// ---------------------------------------------------------------------------
__device__ __forceinline__ void mma_tile(uint32_t sb, uint32_t bufbase,
                                         float acc[5][2][4], int wid, int lane) {
    const int wm = wid >> 3, wn = wid & 7;
    const uint32_t a_lane = (uint32_t)((wm * 80 + (lane & 15)) * (PA * 2) + (lane >> 4) * 16);
    const uint32_t b_lane = (uint32_t)((lane & 15) * (PB * 2) + (wn * 16 + (lane >> 4) * 8) * 2);
    const uint32_t Ab  = sb + SM_A + a_lane;
    const uint32_t Bhb = sb + bufbase + b_lane;
    const uint32_t Blb = Bhb + BSIZE;

#pragma unroll
    for (int k0 = 0; k0 < CDIM; k0 += 16) {
        uint32_t a[5][4];
#pragma unroll
        for (int mi = 0; mi < 5; ++mi)
            ldsm_x4(a[mi], Ab + mi * 16 * (PA * 2) + k0 * 2);
        uint32_t bh[4], bl[4];
        ldsm_x4t(bh, Bhb + k0 * (PB * 2));
        ldsm_x4t(bl, Blb + k0 * (PB * 2));
#pragma unroll
        for (int mi = 0; mi < 5; ++mi) {
            mma16816(acc[mi][0], a[mi], bh);
            mma16816(acc[mi][1], a[mi], bh + 2);
            mma16816(acc[mi][0], a[mi], bl);
            mma16816(acc[mi][1], a[mi], bl + 2);
        }
    }
}

// ---------------------------------------------------------------------------
// Kernel 1: y2 = split( W_cat @ gelu(bn(x)) + b_cat )
// ---------------------------------------------------------------------------
__global__ __launch_bounds__(NTHREADS, 1) void gemm1_mma(
    const float* __restrict__ x,
    const float* __restrict__ gamma, const float* __restrict__ beta,
    const float* __restrict__ rmean, const float* __restrict__ rvar,
    const float* __restrict__ Wt, const float* __restrict__ bt,
    const float* __restrict__ Wb, const float* __restrict__ bb,
    const float* __restrict__ Wr, const float* __restrict__ br,
    const float* __restrict__ Wl, const float* __restrict__ bl,
    const float* __restrict__ Wc, const float* __restrict__ bc) {
    extern __shared__ char smem[];
    const uint32_t sb = smem_u32(smem);
    const int tid = threadIdx.x;
    const int wid = tid >> 5, lane = tid & 31;
    float* bias_s  = (float*)(smem + SM_BIAS);
    float* scale_s = (float*)(smem + SM_SCALE);
    float* shift_s = (float*)(smem + SM_SHIFT);
    __half* Aw = (__half*)(smem + SM_A);

    // weights -> smem fp16, once per CTA
    const float* Wseg[5] = {Wt, Wb, Wr, Wl, Wc};
    for (int idx = tid; idx < CDIM * CDIM; idx += NTHREADS) {
        int m = idx / CDIM;
        int k = idx - m * CDIM;
        Aw[m * PA + k] = __float2half_rn(Wseg[m >> 5][(m & 31) * CDIM + k]);
    }
    if (tid < CDIM) {
        const float* bp[5] = {bt, bb, br, bl, bc};
        bias_s[tid] = bp[tid >> 5][tid & 31];
        float s = gamma[tid] * rsqrtf(rvar[tid] + 1e-5f);
        scale_s[tid] = s;
        shift_s[tid] = beta[tid] - rmean[tid] * s;
    }
    __syncthreads();

    const int px = tid & 127;
    const int kbase = (tid >> 7) * 40;
    const int wm = wid >> 3, wn = wid & 7;
    const int tr = lane >> 2, tc = 2 * (lane & 3);

    // convert one value into buffer
    auto conv = [&](char* buf, int k, float v) {
        float h = fmaf(v, scale_s[k], shift_s[k]);
        float g = 0.5f * h * (1.0f + erff(h * 0.70710678118654752f));
        __half hh = __float2half_rn(g);
        ((__half*)(buf))[k * PB + px] = hh;
        ((__half*)(buf + BSIZE))[k * PB + px] = __float2half_rn(g - __half2float(hh));
    };

    float v0[20], v1[20];

    // prologue: prep tile 0 into buf0
    {
        const float* xb = x + (size_t)((blockIdx.x * TILES_PER_CTA * 128) / HW) * CDIM * HW
                            + (blockIdx.x * TILES_PER_CTA * 128) % HW + px;
#pragma unroll
        for (int j = 0; j < 20; ++j) v0[j] = xb[(size_t)(kbase + j) * HW];
#pragma unroll
        for (int j = 0; j < 20; ++j) v1[j] = xb[(size_t)(kbase + 20 + j) * HW];
#pragma unroll
        for (int j = 0; j < 20; ++j) conv(smem + SM_B0, kbase + j, v0[j]);
#pragma unroll
        for (int j = 0; j < 20; ++j) conv(smem + SM_B0, kbase + 20 + j, v1[j]);
    }
    __syncthreads();

    for (int t = 0; t < TILES_PER_CTA; ++t) {
        const int tile = blockIdx.x * TILES_PER_CTA + t;
        const int b = (tile * 128) / HW;
        const int p0 = tile * 128 - b * HW;
        const uint32_t curbuf = (t & 1) ? SM_B1 : SM_B0;
        char* nxtbuf = smem + ((t & 1) ? SM_B0 : SM_B1);

        // prefetch batch 0 for tile t+1 (latency hides under MMA)
        const float* nxb = nullptr;
        if (t + 1 < TILES_PER_CTA) {
            const int nt = tile + 1;
            const int nb = (nt * 128) / HW;
            nxb = x + (size_t)nb * CDIM * HW + (nt * 128 - nb * HW) + px;
#pragma unroll
            for (int j = 0; j < 20; ++j) v0[j] = nxb[(size_t)(kbase + j) * HW];
        }

        float acc[5][2][4] = {};
        mma_tile(sb, curbuf, acc, wid, lane);

        // batch 1 loads (latency hides under erff-heavy convert of batch 0)
        if (t + 1 < TILES_PER_CTA) {
#pragma unroll
            for (int j = 0; j < 20; ++j) v1[j] = nxb[(size_t)(kbase + 20 + j) * HW];
#pragma unroll
            for (int j = 0; j < 20; ++j) conv(nxtbuf, kbase + j, v0[j]);
#pragma unroll
            for (int j = 0; j < 20; ++j) conv(nxtbuf, kbase + 20 + j, v1[j]);
        }

        // epilogue: +bias, split-pack, direct global stores
        uint32_t* yb = g_y2 + (size_t)b * CDIM * HW + p0;
#pragma unroll
        for (int mi = 0; mi < 5; ++mi) {
            const int r0 = wm * 80 + mi * 16 + tr;
            const float bia0 = bias_s[r0];
            const float bia1 = bias_s[r0 + 8];
#pragma unroll
            for (int ni = 0; ni < 2; ++ni) {
                const int c = wn * 16 + ni * 8 + tc;
                uint2 o;
                o.x = split_pack(acc[mi][ni][0] + bia0);
                o.y = split_pack(acc[mi][ni][1] + bia0);
                *(uint2*)(yb + (size_t)r0 * HW + c) = o;
                o.x = split_pack(acc[mi][ni][2] + bia1);
                o.y = split_pack(acc[mi][ni][3] + bia1);
                *(uint2*)(yb + (size_t)(r0 + 8) * HW + c) = o;
            }
        }
        __syncthreads();
    }
}

// ---------------------------------------------------------------------------
// Kernel 2: out = W_fuse @ shifted_gather(y2) + b_fuse
// ---------------------------------------------------------------------------
__global__ __launch_bounds__(NTHREADS, 1) void gemm2_mma(
    const float* __restrict__ Wf, const float* __restrict__ bf,
    float* __restrict__ out) {
    extern __shared__ char smem[];
    const uint32_t sb = smem_u32(smem);
    const int tid = threadIdx.x;
    const int wid = tid >> 5, lane = tid & 31;
    float* bias_s = (float*)(smem + SM_BIAS);
    __half* Aw = (__half*)(smem + SM_A);

    for (int idx = tid; idx < CDIM * CDIM; idx += NTHREADS) {
        int m = idx / CDIM;
        int k = idx - m * CDIM;
        Aw[m * PA + k] = __float2half_rn(Wf[m * CDIM + k]);
    }
    if (tid < CDIM) bias_s[tid] = bf[tid];
    __syncthreads();

    const int px = tid & 127;
    const int kbase = (tid >> 7) * 40;
    const int wm = wid >> 3, wn = wid & 7;
    const int tr = lane >> 2, tc = 2 * (lane & 3);

    auto gather = [&](const uint32_t* yb, int p, int hr, int w, int k) -> uint32_t {
        const int seg = k >> 5;
        int pp; bool ok;
        if (seg == 0)      { ok = (hr < WIMG - 1); pp = p + WIMG; }
        else if (seg == 1) { ok = (hr > 0);        pp = p - WIMG; }
        else if (seg == 2) { ok = (w > 0);         pp = p - 1;    }
        else if (seg == 3) { ok = (w < WIMG - 1);  pp = p + 1;    }
        else               { ok = true;            pp = p;        }
        return ok ? yb[(size_t)k * HW + pp] : 0u;
    };
    auto conv = [&](char* buf, int k, uint32_t v) {
        ((uint16_t*)(buf))[k * PB + px] = (uint16_t)(v & 0xFFFF);
        ((uint16_t*)(buf + BSIZE))[k * PB + px] = (uint16_t)(v >> 16);
    };

    uint32_t v0[20], v1[20];

    {
        const int tile = blockIdx.x * TILES_PER_CTA;
        const int b = (tile * 128) / HW;
        const int p0 = tile * 128 - b * HW;
        const uint32_t* yb = g_y2 + (size_t)b * CDIM * HW;
        const int p = p0 + px, hr = p / WIMG, w = p - hr * WIMG;
#pragma unroll
        for (int j = 0; j < 20; ++j) v0[j] = gather(yb, p, hr, w, kbase + j);
#pragma unroll
        for (int j = 0; j < 20; ++j) v1[j] = gather(yb, p, hr, w, kbase + 20 + j);
#pragma unroll
        for (int j = 0; j < 20; ++j) conv(smem + SM_B0, kbase + j, v0[j]);
#pragma unroll
        for (int j = 0; j < 20; ++j) conv(smem + SM_B0, kbase + 20 + j, v1[j]);
    }
    __syncthreads();

    for (int t = 0; t < TILES_PER_CTA; ++t) {
        const int tile = blockIdx.x * TILES_PER_CTA + t;
        const int b = (tile * 128) / HW;
        const int p0 = tile * 128 - b * HW;
        const uint32_t curbuf = (t & 1) ? SM_B1 : SM_B0;
        char* nxtbuf = smem + ((t & 1) ? SM_B0 : SM_B1);

        const uint32_t* nyb = nullptr;
        int np = 0, nhr = 0, nw = 0;
        if (t + 1 < TILES_PER_CTA) {
            const int nt = tile + 1;
            const int nb = (nt * 128) / HW;
            const int np0 = nt * 128 - nb * HW;
            nyb = g_y2 + (size_t)nb * CDIM * HW;
            np = np0 + px; nhr = np / WIMG; nw = np - nhr * WIMG;
#pragma unroll
            for (int j = 0; j < 20; ++j) v0[j] = gather(nyb, np, nhr, nw, kbase + j);
        }

        float acc[5][2][4] = {};
        mma_tile(sb, curbuf, acc, wid, lane);

        if (t + 1 < TILES_PER_CTA) {
#pragma unroll
            for (int j = 0; j < 20; ++j) v1[j] = gather(nyb, np, nhr, nw, kbase + 20 + j);
#pragma unroll
            for (int j = 0; j < 20; ++j) conv(nxtbuf, kbase + j, v0[j]);
#pragma unroll
            for (int j = 0; j < 20; ++j) conv(nxtbuf, kbase + 20 + j, v1[j]);
        }

        float* ob = out + (size_t)b * CDIM * HW + p0;
#pragma unroll
        for (int mi = 0; mi < 5; ++mi) {
            const int r0 = wm * 80 + mi * 16 + tr;
            const float bia0 = bias_s[r0];
            const float bia1 = bias_s[r0 + 8];
#pragma unroll
            for (int ni = 0; ni < 2; ++ni) {
                const int c = wn * 16 + ni * 8 + tc;
                *(float2*)(ob + (size_t)r0 * HW + c) =
                    make_float2(acc[mi][ni][0] + bia0, acc[mi][ni][1] + bia0);
                *(float2*)(ob + (size_t)(r0 + 8) * HW + c) =
                    make_float2(acc[mi][ni][2] + bia1, acc[mi][ni][3] + bia1);
            }
        }
        __syncthreads();
    }
}

// ---------------------------------------------------------------------------
extern "C" void kernel_launch(void* const* d_in, const int* in_sizes, int n_in,
                              void* d_out, int out_size) {
    const float* x     = (const float*)d_in[0];
    const float* gamma = (const float*)d_in[1];
    const float* beta  = (const float*)d_in[2];
    const float* rmean = (const float*)d_in[3];
    const float* rvar  = (const float*)d_in[4];
    const float* Wt = (const float*)d_in[5];  const float* bt = (const float*)d_in[6];
    const float* Wb = (const float*)d_in[7];  const float* bb = (const float*)d_in[8];
    const float* Wr = (const float*)d_in[9];  const float* br = (const float*)d_in[10];
    const float* Wl = (const float*)d_in[11]; const float* bl = (const float*)d_in[12];
    const float* Wc = (const float*)d_in[13]; const float* bc = (const float*)d_in[14];
    const float* Wf = (const float*)d_in[15]; const float* bf = (const float*)d_in[16];

    cudaFuncSetAttribute(gemm1_mma, cudaFuncAttributeMaxDynamicSharedMemorySize, SM_TOTAL);
    cudaFuncSetAttribute(gemm2_mma, cudaFuncAttributeMaxDynamicSharedMemorySize, SM_TOTAL);

    gemm1_mma<<<NBLOCKS, NTHREADS, SM_TOTAL>>>(x, gamma, beta, rmean, rvar,
                                               Wt, bt, Wb, bb, Wr, br, Wl, bl, Wc, bc);
    gemm2_mma<<<NBLOCKS, NTHREADS, SM_TOTAL>>>(Wf, bf, (float*)d_out);
}

// round 6
// speedup vs baseline: 4.8442x; 1.0776x over previous
#include <cuda_runtime.h>
#include <cuda_fp16.h>
#include <math.h>
#include <cstdint>

#define CDIM 160
#define HW 12544
#define WIMG 112
#define NIMG 32
#define NTHREADS 256
#define TILE_PX 64
#define TILES_PER_CTA 7
#define NBLOCKS 896          // 896 * 7 * 64px = 32*12544 px

#define PA 168      // A smem pitch (fp16) -> 336B rows, conflict-free ldmatrix
#define PB 72       // B smem pitch (fp16) -> 144B rows, conflict-free ldmatrix.trans
#define BSIZE (CDIM * PB * 2)   // 23040 bytes, one B tile

// shared memory byte offsets
#define SM_BIAS  0
#define SM_SCALE 640
#define SM_SHIFT 1280
#define SM_A     2048                       // 160*168*2 = 53760
#define SM_B0    (SM_A + CDIM * PA * 2)     // 55808
#define SM_B1    (SM_B0 + BSIZE)            // 78848
#define SM_TOTAL (SM_B1 + BSIZE)            // 101888  (2 CTAs/SM: 203776 < 228K)

// intermediate y = gelu-path output, channel-major [b][c][hw], fp16
__device__ __half g_yh[(size_t)NIMG * CDIM * HW];

// ---------------------------------------------------------------------------
__device__ __forceinline__ uint32_t smem_u32(const void* p) {
    uint32_t a;
    asm("{ .reg .u64 t; cvta.to.shared.u64 t, %1; cvt.u32.u64 %0, t; }" : "=r"(a) : "l"(p));
    return a;
}
__device__ __forceinline__ void ldsm_x4(uint32_t* r, uint32_t addr) {
    asm volatile("ldmatrix.sync.aligned.m8n8.x4.shared.b16 {%0,%1,%2,%3}, [%4];"
        : "=r"(r[0]), "=r"(r[1]), "=r"(r[2]), "=r"(r[3]) : "r"(addr));
}
__device__ __forceinline__ void ldsm_x4t(uint32_t* r, uint32_t addr) {
    asm volatile("ldmatrix.sync.aligned.m8n8.x4.trans.shared.b16 {%0,%1,%2,%3}, [%4];"
        : "=r"(r[0]), "=r"(r[1]), "=r"(r[2]), "=r"(r[3]) : "r"(addr));
}
__device__ __forceinline__ void mma16816(float* d, const uint32_t* a, const uint32_t* b) {
    asm volatile("mma.sync.aligned.m16n8k16.row.col.f32.f16.f16.f32 "
        "{%0,%1,%2,%3}, {%4,%5,%6,%7}, {%8,%9}, {%0,%1,%2,%3};"
        : "+f"(d[0]), "+f"(d[1]), "+f"(d[2]), "+f"(d[3])
        : "r"(a[0]), "r"(a[1]), "r"(a[2]), "r"(a[3]), "r"(b[0]), "r"(b[1]));
}

// ---------------------------------------------------------------------------
// 1-pass fp16 MMA over a 160(ch) x 64(px) tile. 8 warps: 2M x 4N.
// Each warp: 5 m-tiles x 2 n-tiles. Per k0: 5 A-ldsm + 1 B-ldsm + 10 HMMA.
// ---------------------------------------------------------------------------
__device__ __forceinline__ void mma_tile(uint32_t sb, uint32_t bufbase,
                                         float acc[5][2][4], int wid, int lane) {
    const int wm = wid >> 2, wn = wid & 3;
    const uint32_t a_lane = (uint32_t)((wm * 80 + (lane & 15)) * (PA * 2) + (lane >> 4) * 16);
    const uint32_t b_lane = (uint32_t)((lane & 15) * (PB * 2) + (wn * 16 + (lane >> 4) * 8) * 2);
    const uint32_t Ab = sb + SM_A + a_lane;
    const uint32_t Bb = sb + bufbase + b_lane;

#pragma unroll
    for (int k0 = 0; k0 < CDIM; k0 += 16) {
        uint32_t a[5][4];
#pragma unroll
        for (int mi = 0; mi < 5; ++mi)
            ldsm_x4(a[mi], Ab + mi * 16 * (PA * 2) + k0 * 2);
        uint32_t b[4];
        ldsm_x4t(b, Bb + k0 * (PB * 2));
#pragma unroll
        for (int mi = 0; mi < 5; ++mi) {
            mma16816(acc[mi][0], a[mi], b);
            mma16816(acc[mi][1], a[mi], b + 2);
        }
    }
}

// ---------------------------------------------------------------------------
// Kernel 1: y = fp16( W_cat @ gelu(bn(x)) + b_cat )
// ---------------------------------------------------------------------------
__global__ __launch_bounds__(NTHREADS, 2) void gemm1_mma(
    const float* __restrict__ x,
    const float* __restrict__ gamma, const float* __restrict__ beta,
    const float* __restrict__ rmean, const float* __restrict__ rvar,
    const float* __restrict__ Wt, const float* __restrict__ bt,
    const float* __restrict__ Wb, const float* __restrict__ bb,
    const float* __restrict__ Wr, const float* __restrict__ br,
    const float* __restrict__ Wl, const float* __restrict__ bl,
    const float* __restrict__ Wc, const float* __restrict__ bc) {
    extern __shared__ char smem[];
    const uint32_t sb = smem_u32(smem);
    const int tid = threadIdx.x;
    const int wid = tid >> 5, lane = tid & 31;
    float* bias_s  = (float*)(smem + SM_BIAS);
    float* scale_s = (float*)(smem + SM_SCALE);
    float* shift_s = (float*)(smem + SM_SHIFT);
    __half* Aw = (__half*)(smem + SM_A);

    // weights -> smem fp16, once per CTA
    const float* Wseg[5] = {Wt, Wb, Wr, Wl, Wc};
    for (int idx = tid; idx < CDIM * CDIM; idx += NTHREADS) {
        int m = idx / CDIM;
        int k = idx - m * CDIM;
        Aw[m * PA + k] = __float2half_rn(Wseg[m >> 5][(m & 31) * CDIM + k]);
    }
    if (tid < CDIM) {
        const float* bp[5] = {bt, bb, br, bl, bc};
        bias_s[tid] = bp[tid >> 5][tid & 31];
        float s = gamma[tid] * rsqrtf(rvar[tid] + 1e-5f);
        scale_s[tid] = s;
        shift_s[tid] = beta[tid] - rmean[tid] * s;
    }
    __syncthreads();

    const int px = tid & 63;
    const int kbase = (tid >> 6) * 40;
    const int wm = wid >> 2, wn = wid & 3;
    const int tr = lane >> 2, tc = 2 * (lane & 3);

    auto conv = [&](char* buf, int k, float v) {
        float h = fmaf(v, scale_s[k], shift_s[k]);
        float g = 0.5f * h * (1.0f + erff(h * 0.70710678118654752f));
        ((__half*)(buf))[k * PB + px] = __float2half_rn(g);
    };

    float v0[20], v1[20];

    // prologue: prep tile 0 into buf0
    {
        const int tile = blockIdx.x * TILES_PER_CTA;
        const int b = (tile * TILE_PX) / HW;
        const int p0 = tile * TILE_PX - b * HW;
        const float* xb = x + (size_t)b * CDIM * HW + p0 + px;
#pragma unroll
        for (int j = 0; j < 20; ++j) v0[j] = xb[(size_t)(kbase + j) * HW];
#pragma unroll
        for (int j = 0; j < 20; ++j) v1[j] = xb[(size_t)(kbase + 20 + j) * HW];
#pragma unroll
        for (int j = 0; j < 20; ++j) conv(smem + SM_B0, kbase + j, v0[j]);
#pragma unroll
        for (int j = 0; j < 20; ++j) conv(smem + SM_B0, kbase + 20 + j, v1[j]);
    }
    __syncthreads();

    for (int t = 0; t < TILES_PER_CTA; ++t) {
        const int tile = blockIdx.x * TILES_PER_CTA + t;
        const int b = (tile * TILE_PX) / HW;
        const int p0 = tile * TILE_PX - b * HW;
        const uint32_t curbuf = (t & 1) ? SM_B1 : SM_B0;
        char* nxtbuf = smem + ((t & 1) ? SM_B0 : SM_B1);

        // prefetch batch 0 for tile t+1 (latency hides under MMA)
        const float* nxb = nullptr;
        if (t + 1 < TILES_PER_CTA) {
            const int nt = tile + 1;
            const int nb = (nt * TILE_PX) / HW;
            nxb = x + (size_t)nb * CDIM * HW + (nt * TILE_PX - nb * HW) + px;
#pragma unroll
            for (int j = 0; j < 20; ++j) v0[j] = nxb[(size_t)(kbase + j) * HW];
        }

        float acc[5][2][4] = {};
        mma_tile(sb, curbuf, acc, wid, lane);

        if (t + 1 < TILES_PER_CTA) {
#pragma unroll
            for (int j = 0; j < 20; ++j) v1[j] = nxb[(size_t)(kbase + 20 + j) * HW];
#pragma unroll
            for (int j = 0; j < 20; ++j) conv(nxtbuf, kbase + j, v0[j]);
#pragma unroll
            for (int j = 0; j < 20; ++j) conv(nxtbuf, kbase + 20 + j, v1[j]);
        }

        // epilogue: +bias -> fp16, packed 2-px stores
        __half* yb = g_yh + (size_t)b * CDIM * HW + p0;
#pragma unroll
        for (int mi = 0; mi < 5; ++mi) {
            const int r0 = wm * 80 + mi * 16 + tr;
            const float bia0 = bias_s[r0];
            const float bia1 = bias_s[r0 + 8];
#pragma unroll
            for (int ni = 0; ni < 2; ++ni) {
                const int c = wn * 16 + ni * 8 + tc;
                __half2 o0 = __floats2half2_rn(acc[mi][ni][0] + bia0, acc[mi][ni][1] + bia0);
                *(__half2*)(yb + (size_t)r0 * HW + c) = o0;
                __half2 o1 = __floats2half2_rn(acc[mi][ni][2] + bia1, acc[mi][ni][3] + bia1);
                *(__half2*)(yb + (size_t)(r0 + 8) * HW + c) = o1;
            }
        }
        __syncthreads();
    }
}

// ---------------------------------------------------------------------------
// Kernel 2: out = W_fuse @ shifted_gather(y) + b_fuse
// ---------------------------------------------------------------------------
__global__ __launch_bounds__(NTHREADS, 2) void gemm2_mma(
    const float* __restrict__ Wf, const float* __restrict__ bf,
    float* __restrict__ out) {
    extern __shared__ char smem[];
    const uint32_t sb = smem_u32(smem);
    const int tid = threadIdx.x;
    const int wid = tid >> 5, lane = tid & 31;
    float* bias_s = (float*)(smem + SM_BIAS);
    __half* Aw = (__half*)(smem + SM_A);

    for (int idx = tid; idx < CDIM * CDIM; idx += NTHREADS) {
        int m = idx / CDIM;
        int k = idx - m * CDIM;
        Aw[m * PA + k] = __float2half_rn(Wf[m * CDIM + k]);
    }
    if (tid < CDIM) bias_s[tid] = bf[tid];
    __syncthreads();

    const int px = tid & 63;
    const int kbase = (tid >> 6) * 40;
    const int wm = wid >> 2, wn = wid & 3;
    const int tr = lane >> 2, tc = 2 * (lane & 3);

    auto gather = [&](const __half* yb, int p, int hr, int w, int k) -> uint16_t {
        const int seg = k >> 5;
        int pp; bool ok;
        if (seg == 0)      { ok = (hr < WIMG - 1); pp = p + WIMG; }
        else if (seg == 1) { ok = (hr > 0);        pp = p - WIMG; }
        else if (seg == 2) { ok = (w > 0);         pp = p - 1;    }
        else if (seg == 3) { ok = (w < WIMG - 1);  pp = p + 1;    }
        else               { ok = true;            pp = p;        }
        return ok ? *(const uint16_t*)(yb + (size_t)k * HW + pp) : (uint16_t)0;
    };
    auto conv = [&](char* buf, int k, uint16_t v) {
        ((uint16_t*)(buf))[k * PB + px] = v;
    };

    uint16_t v0[20], v1[20];

    {
        const int tile = blockIdx.x * TILES_PER_CTA;
        const int b = (tile * TILE_PX) / HW;
        const int p0 = tile * TILE_PX - b * HW;
        const __half* yb = g_yh + (size_t)b * CDIM * HW;
        const int p = p0 + px, hr = p / WIMG, w = p - hr * WIMG;
#pragma unroll
        for (int j = 0; j < 20; ++j) v0[j] = gather(yb, p, hr, w, kbase + j);
#pragma unroll
        for (int j = 0; j < 20; ++j) v1[j] = gather(yb, p, hr, w, kbase + 20 + j);
#pragma unroll
        for (int j = 0; j < 20; ++j) conv(smem + SM_B0, kbase + j, v0[j]);
#pragma unroll
        for (int j = 0; j < 20; ++j) conv(smem + SM_B0, kbase + 20 + j, v1[j]);
    }
    __syncthreads();

    for (int t = 0; t < TILES_PER_CTA; ++t) {
        const int tile = blockIdx.x * TILES_PER_CTA + t;
        const int b = (tile * TILE_PX) / HW;
        const int p0 = tile * TILE_PX - b * HW;
        const uint32_t curbuf = (t & 1) ? SM_B1 : SM_B0;
        char* nxtbuf = smem + ((t & 1) ? SM_B0 : SM_B1);

        const __half* nyb = nullptr;
        int np = 0, nhr = 0, nw = 0;
        if (t + 1 < TILES_PER_CTA) {
            const int nt = tile + 1;
            const int nb = (nt * TILE_PX) / HW;
            const int np0 = nt * TILE_PX - nb * HW;
            nyb = g_yh + (size_t)nb * CDIM * HW;
            np = np0 + px; nhr = np / WIMG; nw = np - nhr * WIMG;
#pragma unroll
            for (int j = 0; j < 20; ++j) v0[j] = gather(nyb, np, nhr, nw, kbase + j);
        }

        float acc[5][2][4] = {};
        mma_tile(sb, curbuf, acc, wid, lane);

        if (t + 1 < TILES_PER_CTA) {
#pragma unroll
            for (int j = 0; j < 20; ++j) v1[j] = gather(nyb, np, nhr, nw, kbase + 20 + j);
#pragma unroll
            for (int j = 0; j < 20; ++j) conv(nxtbuf, kbase + j, v0[j]);
#pragma unroll
            for (int j = 0; j < 20; ++j) conv(nxtbuf, kbase + 20 + j, v1[j]);
        }

        float* ob = out + (size_t)b * CDIM * HW + p0;
#pragma unroll
        for (int mi = 0; mi < 5; ++mi) {
            const int r0 = wm * 80 + mi * 16 + tr;
            const float bia0 = bias_s[r0];
            const float bia1 = bias_s[r0 + 8];
#pragma unroll
            for (int ni = 0; ni < 2; ++ni) {
                const int c = wn * 16 + ni * 8 + tc;
                *(float2*)(ob + (size_t)r0 * HW + c) =
                    make_float2(acc[mi][ni][0] + bia0, acc[mi][ni][1] + bia0);
                *(float2*)(ob + (size_t)(r0 + 8) * HW + c) =
                    make_float2(acc[mi][ni][2] + bia1, acc[mi][ni][3] + bia1);
            }
        }
        __syncthreads();
    }
}

// ---------------------------------------------------------------------------
extern "C" void kernel_launch(void* const* d_in, const int* in_sizes, int n_in,
                              void* d_out, int out_size) {
    const float* x     = (const float*)d_in[0];
    const float* gamma = (const float*)d_in[1];
    const float* beta  = (const float*)d_in[2];
    const float* rmean = (const float*)d_in[3];
    const float* rvar  = (const float*)d_in[4];
    const float* Wt = (const float*)d_in[5];  const float* bt = (const float*)d_in[6];
    const float* Wb = (const float*)d_in[7];  const float* bb = (const float*)d_in[8];
    const float* Wr = (const float*)d_in[9];  const float* br = (const float*)d_in[10];
    const float* Wl = (const float*)d_in[11]; const float* bl = (const float*)d_in[12];
    const float* Wc = (const float*)d_in[13]; const float* bc = (const float*)d_in[14];
    const float* Wf = (const float*)d_in[15]; const float* bf = (const float*)d_in[16];

    cudaFuncSetAttribute(gemm1_mma, cudaFuncAttributeMaxDynamicSharedMemorySize, SM_TOTAL);
    cudaFuncSetAttribute(gemm2_mma, cudaFuncAttributeMaxDynamicSharedMemorySize, SM_TOTAL);

    gemm1_mma<<<NBLOCKS, NTHREADS, SM_TOTAL>>>(x, gamma, beta, rmean, rvar,
                                               Wt, bt, Wb, bb, Wr, br, Wl, bl, Wc, bc);
    gemm2_mma<<<NBLOCKS, NTHREADS, SM_TOTAL>>>(Wf, bf, (float*)d_out);
}